// round 16
// baseline (speedup 1.0000x reference)
#include <cuda_runtime.h>
#include <cuda_bf16.h>
#include <cstdint>

#define SHIFT 4
#define NR 225
#define AS 132
#define ES 36
#define TS 40            // embed table row stride (bf16 elems) = 20 u32
#define GS 232           // G row stride (bf16 elems) = 116 u32
#define SCALE 0.17677669529663687f

// smem byte offsets
#define SA_B   0          // fp32 attn 128x132 (67584)
#define QH_B   67584      // bf16 q hi token-major 20u32/row (10240)
#define QL_B   77824
#define KH_B   88064
#define KL_B   98304      // ends 108544
#define QEB_B  108544     // bf16 q_embed 225x40 (18432)
#define KEB_B  126976     // bf16 k_embed
#define VEB_B  145408     // bf16 v_embed -> ends 163840
#define G_B    163840     // bf16 G 128x232 (59392) -> ends 223232
#define SMEM_BYTES 223232
// overlays
#define AH_B   67584      // bf16 attn hi 128x68u32 (34816)  [over qk tiles, dead after G2]
#define AL_B   102400     // bf16 attn lo (34816)            [over KL tail+QE+KE, dead after G2]
#define VTH_B  163840     // bf16 V^T hi 32x136 (8704)       [over G, dead after kr gather]
#define VTL_B  172544
#define OE_B   181248     // fp32 embed partial 128x36 (18432) [over G]

__device__ __forceinline__ void mma_bf16(float* d, uint32_t a0, uint32_t a1, uint32_t a2, uint32_t a3,
                                         uint32_t b0, uint32_t b1) {
    asm volatile(
        "mma.sync.aligned.m16n8k16.row.col.f32.bf16.bf16.f32 "
        "{%0,%1,%2,%3},{%4,%5,%6,%7},{%8,%9},{%0,%1,%2,%3};"
        : "+f"(d[0]), "+f"(d[1]), "+f"(d[2]), "+f"(d[3])
        : "r"(a0), "r"(a1), "r"(a2), "r"(a3), "r"(b0), "r"(b1));
}
__device__ __forceinline__ uint32_t pkhi(float a, float b) {
    __nv_bfloat162 t = __floats2bfloat162_rn(a, b);
    return *reinterpret_cast<uint32_t*>(&t);
}
__device__ __forceinline__ uint32_t pklo(float a, float b) {
    float ha = __bfloat162float(__float2bfloat16(a));
    float hb = __bfloat162float(__float2bfloat16(b));
    __nv_bfloat162 t = __floats2bfloat162_rn(a - ha, b - hb);
    return *reinterpret_cast<uint32_t*>(&t);
}
__device__ __forceinline__ float2 upk(uint32_t h) {
    return __bfloat1622float2(*reinterpret_cast<__nv_bfloat162*>(&h));
}

__global__ __launch_bounds__(256, 1)
void swin_attn_kernel(const float* __restrict__ qkv,
                      const float* __restrict__ mask,
                      const float* __restrict__ rpe,
                      float* __restrict__ out)
{
    extern __shared__ char smc[];
    float* sA  = (float*)(smc + SA_B);
    __nv_bfloat16* QEb = (__nv_bfloat16*)(smc + QEB_B);
    __nv_bfloat16* KEb = (__nv_bfloat16*)(smc + KEB_B);
    __nv_bfloat16* VEb = (__nv_bfloat16*)(smc + VEB_B);
    uint32_t* QEu = (uint32_t*)(smc + QEB_B);
    uint32_t* KEu = (uint32_t*)(smc + KEB_B);
    uint32_t* VEu = (uint32_t*)(smc + VEB_B);
    uint32_t* Gu  = (uint32_t*)(smc + G_B);
    __nv_bfloat16* Gb = (__nv_bfloat16*)(smc + G_B);
    float* sOE = (float*)(smc + OE_B);
    uint32_t* QHu = (uint32_t*)(smc + QH_B);
    uint32_t* QLu = (uint32_t*)(smc + QL_B);
    uint32_t* KHu = (uint32_t*)(smc + KH_B);
    uint32_t* KLu = (uint32_t*)(smc + KL_B);
    uint32_t* AHu = (uint32_t*)(smc + AH_B);
    uint32_t* ALu = (uint32_t*)(smc + AL_B);
    uint32_t* VTHu = (uint32_t*)(smc + VTH_B);
    uint32_t* VTLu = (uint32_t*)(smc + VTL_B);

    const int tid = threadIdx.x, wid = tid >> 5, lane = tid & 31;
    const int h   = blockIdx.y;
    const int b   = blockIdx.x >> 8;
    const int win = blockIdx.x & 255;
    const int wi  = win >> 4, wj = win & 15;

    // ---- phase 1: load q,k hi/lo bf16 (token-major); NOT v yet ----
    {
        const int t = tid >> 1, half = tid & 1;
        const int wh = t >> 4, ww = (t >> 1) & 7, n = t & 1;
        const int gy = (wi*8 + wh + SHIFT) & 127;
        const int gx = (wj*8 + ww + SHIFT) & 127;
        const float* base = qkv + (size_t)((((b*128 + gy)*128 + gx)*2 + n)*384) + h*32 + half*16;
        #pragma unroll
        for (int c4 = 0; c4 < 4; c4++) {
            float4 q = ((const float4*)base)[c4];
            float4 k = ((const float4*)(base + 128))[c4];
            q.x *= SCALE; q.y *= SCALE; q.z *= SCALE; q.w *= SCALE;
            const int u = t*20 + half*8 + c4*2;
            QHu[u]   = pkhi(q.x, q.y); QHu[u+1] = pkhi(q.z, q.w);
            QLu[u]   = pklo(q.x, q.y); QLu[u+1] = pklo(q.z, q.w);
            KHu[u]   = pkhi(k.x, k.y); KHu[u+1] = pkhi(k.z, k.w);
            KLu[u]   = pklo(k.x, k.y); KLu[u+1] = pklo(k.z, k.w);
        }
    }
    // ---- rel-pos tables -> bf16 ----
    for (int idx = tid; idx < NR*24; idx += 256) {
        const int r = idx / 24, s = idx % 24;
        const int sl = s >> 3, c4 = s & 7;
        float4 v = *(const float4*)(rpe + (size_t)r*384 + h*96 + sl*32 + c4*4);
        __nv_bfloat16* dst = (sl == 0) ? QEb : (sl == 1) ? KEb : VEb;
        if (sl == 0) { v.x *= SCALE; v.y *= SCALE; v.z *= SCALE; v.w *= SCALE; }
        uint2 pk;
        pk.x = pkhi(v.x, v.y); pk.y = pkhi(v.z, v.w);
        *(uint2*)(dst + r*TS + c4*4) = pk;
    }
    __syncthreads();

    // ---- phase 2: qk via mma.sync (hi/lo 3-mma), +mask -> sA ----
    {
        const int r0 = wid*16, r = lane >> 2, cq = lane & 3;
        uint32_t ah[2][4], al[2][4];
        #pragma unroll
        for (int kt = 0; kt < 2; kt++) {
            const int base0 = (r0 + r)*20 + kt*8 + cq;
            const int base1 = (r0 + r + 8)*20 + kt*8 + cq;
            ah[kt][0] = QHu[base0];     ah[kt][1] = QHu[base1];
            ah[kt][2] = QHu[base0 + 4]; ah[kt][3] = QHu[base1 + 4];
            al[kt][0] = QLu[base0];     al[kt][1] = QLu[base1];
            al[kt][2] = QLu[base0 + 4]; al[kt][3] = QLu[base1 + 4];
        }
        const float* mrow = mask + (size_t)win*16384;
        #pragma unroll
        for (int nt = 0; nt < 16; nt++) {
            float d[4] = {0.f, 0.f, 0.f, 0.f};
            #pragma unroll
            for (int kt = 0; kt < 2; kt++) {
                const int bidx = (nt*8 + r)*20 + kt*8 + cq;
                uint32_t bh0 = KHu[bidx], bh1 = KHu[bidx + 4];
                uint32_t bl0 = KLu[bidx], bl1 = KLu[bidx + 4];
                mma_bf16(d, ah[kt][0], ah[kt][1], ah[kt][2], ah[kt][3], bh0, bh1);
                mma_bf16(d, al[kt][0], al[kt][1], al[kt][2], al[kt][3], bh0, bh1);
                mma_bf16(d, ah[kt][0], ah[kt][1], ah[kt][2], ah[kt][3], bl0, bl1);
            }
            const int j0 = nt*8 + cq*2;
            const int i0 = r0 + r, i1 = r0 + r + 8;
            float2 m0 = *(const float2*)(mrow + i0*128 + j0);
            float2 m1 = *(const float2*)(mrow + i1*128 + j0);
            *(float2*)(sA + i0*AS + j0) = make_float2(d[0] + m0.x, d[1] + m0.y);
            *(float2*)(sA + i1*AS + j0) = make_float2(d[2] + m1.x, d[3] + m1.y);
        }
    }
    __syncthreads();

    // ---- phase 3: G1 = Qh @ KEh^T (single-bf16, 128x232x32) -> G ----
    {
        const int r0 = wid*16, r = lane >> 2, cq = lane & 3;
        uint32_t a[2][4];
        #pragma unroll
        for (int kt = 0; kt < 2; kt++) {
            const int base0 = (r0 + r)*20 + kt*8 + cq;
            const int base1 = base0 + 160;
            a[kt][0] = QHu[base0]; a[kt][1] = QHu[base1];
            a[kt][2] = QHu[base0 + 4]; a[kt][3] = QHu[base1 + 4];
        }
        #pragma unroll 4
        for (int nt = 0; nt < 29; nt++) {
            float d[4] = {0.f, 0.f, 0.f, 0.f};
            #pragma unroll
            for (int kt = 0; kt < 2; kt++) {
                const int bidx = (nt*8 + r)*20 + kt*8 + cq;
                mma_bf16(d, a[kt][0], a[kt][1], a[kt][2], a[kt][3], KEu[bidx], KEu[bidx + 4]);
            }
            const int jh = nt*4 + cq;  // u32 column of G
            Gu[(r0 + r)*116 + jh]     = pkhi(d[0], d[1]);
            Gu[(r0 + r + 8)*116 + jh] = pkhi(d[2], d[3]);
        }
    }
    __syncthreads();

    // ---- phase 4: gather qr -> sA ----
    {
        const int p = tid >> 2, pj0 = (tid & 3) << 4;
        const int phi = p >> 3, pwi = p & 7, i0 = 2*p;
        #pragma unroll 4
        for (int pj = pj0; pj < pj0 + 16; pj++) {
            const int r = (phi - (pj >> 3) + 7)*15 + (pwi - (pj & 7) + 7);
            float s0 = __bfloat162float(Gb[i0*GS + r]);
            float s1 = __bfloat162float(Gb[(i0+1)*GS + r]);
            float2* d0 = (float2*)(sA + i0*AS + 2*pj);
            float2* d1 = (float2*)(sA + (i0+1)*AS + 2*pj);
            float2 t0 = *d0, t1 = *d1;
            t0.x += s0; t0.y += s0; *d0 = t0;
            t1.x += s1; t1.y += s1; *d1 = t1;
        }
    }
    __syncthreads();

    // ---- phase 5: G2 = Kh @ QEh^T -> G ----
    {
        const int r0 = wid*16, r = lane >> 2, cq = lane & 3;
        uint32_t a[2][4];
        #pragma unroll
        for (int kt = 0; kt < 2; kt++) {
            const int base0 = (r0 + r)*20 + kt*8 + cq;
            const int base1 = base0 + 160;
            a[kt][0] = KHu[base0]; a[kt][1] = KHu[base1];
            a[kt][2] = KHu[base0 + 4]; a[kt][3] = KHu[base1 + 4];
        }
        #pragma unroll 4
        for (int nt = 0; nt < 29; nt++) {
            float d[4] = {0.f, 0.f, 0.f, 0.f};
            #pragma unroll
            for (int kt = 0; kt < 2; kt++) {
                const int bidx = (nt*8 + r)*20 + kt*8 + cq;
                mma_bf16(d, a[kt][0], a[kt][1], a[kt][2], a[kt][3], QEu[bidx], QEu[bidx + 4]);
            }
            const int jh = nt*4 + cq;
            Gu[(r0 + r)*116 + jh]     = pkhi(d[0], d[1]);
            Gu[(r0 + r + 8)*116 + jh] = pkhi(d[2], d[3]);
        }
    }
    __syncthreads();

    // ---- phase 6: gather kr -> sA ----
    {
        const int p = tid >> 2, pi0 = (tid & 3) << 4;
        const int phj = p >> 3, pwj = p & 7, j0 = 2*p;
        #pragma unroll 4
        for (int pi = pi0; pi < pi0 + 16; pi++) {
            const int r = ((pi >> 3) - phj + 7)*15 + ((pi & 7) - pwj + 7);
            float s0 = __bfloat162float(Gb[j0*GS + r]);
            float s1 = __bfloat162float(Gb[(j0+1)*GS + r]);
            float2* d0 = (float2*)(sA + (2*pi)*AS + j0);
            float2* d1 = (float2*)(sA + (2*pi+1)*AS + j0);
            float2 t0 = *d0, t1 = *d1;
            t0.x += s0; t0.y += s1; *d0 = t0;
            t1.x += s0; t1.y += s1; *d1 = t1;
        }
    }
    __syncthreads();

    // ---- phase 7: load V -> VT hi/lo (over dead G) + fused softmax/emit/pair-sum ----
    {
        const int t = tid >> 1, half = tid & 1;
        const int wh = t >> 4, ww = (t >> 1) & 7, n = t & 1;
        const int gy = (wi*8 + wh + SHIFT) & 127;
        const int gx = (wj*8 + ww + SHIFT) & 127;
        const float* vbase = qkv + (size_t)((((b*128 + gy)*128 + gx)*2 + n)*384) + 256 + h*32 + half*16;
        #pragma unroll
        for (int c4 = 0; c4 < 4; c4++) {
            float4 v = ((const float4*)vbase)[c4];
            float vv[4] = {v.x, v.y, v.z, v.w};
            #pragma unroll
            for (int e = 0; e < 4; e++) {
                const int c = half*16 + c4*4 + e;
                __nv_bfloat16 hi = __float2bfloat16(vv[e]);
                __nv_bfloat16 lo = __float2bfloat16(vv[e] - __bfloat162float(hi));
                ((__nv_bfloat16*)VTHu)[c*136 + t] = hi;
                ((__nv_bfloat16*)VTLu)[c*136 + t] = lo;
            }
        }
    }
    {
        const int w = tid >> 5, l = lane;
        for (int ii = 0; ii < 16; ii++) {
            const int i = w*16 + ii;
            float2 v01 = *(const float2*)(sA + i*AS + 2*l);
            float2 v23 = *(const float2*)(sA + i*AS + 64 + 2*l);
            float m = fmaxf(fmaxf(v01.x, v01.y), fmaxf(v23.x, v23.y));
            #pragma unroll
            for (int off = 16; off; off >>= 1) m = fmaxf(m, __shfl_xor_sync(~0u, m, off));
            float e0 = __expf(v01.x - m), e1 = __expf(v01.y - m);
            float e2 = __expf(v23.x - m), e3 = __expf(v23.y - m);
            float s = e0 + e1 + e2 + e3;
            #pragma unroll
            for (int off = 16; off; off >>= 1) s += __shfl_xor_sync(~0u, s, off);
            const float inv = 1.f / s;
            e0 *= inv; e1 *= inv; e2 *= inv; e3 *= inv;
            AHu[i*68 + l]      = pkhi(e0, e1);
            ALu[i*68 + l]      = pklo(e0, e1);
            AHu[i*68 + 32 + l] = pkhi(e2, e3);
            ALu[i*68 + 32 + l] = pklo(e2, e3);
            sA[i*AS + l]       = e0 + e1;
            sA[i*AS + 32 + l]  = e2 + e3;
        }
    }
    __syncthreads();

    // ---- phase 8: scalar v_embed term (pair sums x VE) -> sOE ----
    {
        const int p = tid >> 2, c0 = (tid & 3) << 3;
        const int phi = p >> 3, pwi = p & 7, i0 = 2*p;
        float4 a0a = {0,0,0,0}, a0b = {0,0,0,0}, a1a = {0,0,0,0}, a1b = {0,0,0,0};
        #pragma unroll 4
        for (int pj = 0; pj < 64; pj++) {
            const float s0 = sA[i0*AS + pj];
            const float s1 = sA[(i0+1)*AS + pj];
            const int r = (phi - (pj >> 3) + 7)*15 + (pwi - (pj & 7) + 7);
            uint2 ea = *(const uint2*)(VEb + r*TS + c0);
            uint2 eb = *(const uint2*)(VEb + r*TS + c0 + 4);
            float2 e0 = upk(ea.x), e1 = upk(ea.y), e2 = upk(eb.x), e3 = upk(eb.y);
            a0a.x += s0*e0.x; a0a.y += s0*e0.y; a0a.z += s0*e1.x; a0a.w += s0*e1.y;
            a0b.x += s0*e2.x; a0b.y += s0*e2.y; a0b.z += s0*e3.x; a0b.w += s0*e3.y;
            a1a.x += s1*e0.x; a1a.y += s1*e0.y; a1a.z += s1*e1.x; a1a.w += s1*e1.y;
            a1b.x += s1*e2.x; a1b.y += s1*e2.y; a1b.z += s1*e3.x; a1b.w += s1*e3.y;
        }
        *(float4*)(sOE + i0*ES + c0)         = a0a;
        *(float4*)(sOE + i0*ES + c0 + 4)     = a0b;
        *(float4*)(sOE + (i0+1)*ES + c0)     = a1a;
        *(float4*)(sOE + (i0+1)*ES + c0 + 4) = a1b;
    }
    __syncthreads();

    // ---- phase 9: AV via mma.sync + add embed partial + store ----
    {
        const int r0 = wid*16, r = lane >> 2, cq = lane & 3;
        float d[4][4];
        #pragma unroll
        for (int nt = 0; nt < 4; nt++)
            #pragma unroll
            for (int e = 0; e < 4; e++) d[nt][e] = 0.f;
        #pragma unroll
        for (int kt = 0; kt < 8; kt++) {
            const int a0i = (r0 + r)*68 + kt*8 + cq;
            const int a1i = (r0 + r + 8)*68 + kt*8 + cq;
            uint32_t ah0 = AHu[a0i], ah1 = AHu[a1i], ah2 = AHu[a0i + 4], ah3 = AHu[a1i + 4];
            uint32_t al0 = ALu[a0i], al1 = ALu[a1i], al2 = ALu[a0i + 4], al3 = ALu[a1i + 4];
            #pragma unroll
            for (int nt = 0; nt < 4; nt++) {
                const int bidx = (nt*8 + r)*68 + kt*8 + cq;
                uint32_t bh0 = VTHu[bidx], bh1 = VTHu[bidx + 4];
                uint32_t bl0 = VTLu[bidx], bl1 = VTLu[bidx + 4];
                mma_bf16(d[nt], ah0, ah1, ah2, ah3, bh0, bh1);
                mma_bf16(d[nt], al0, al1, al2, al3, bh0, bh1);
                mma_bf16(d[nt], ah0, ah1, ah2, ah3, bl0, bl1);
            }
        }
        #pragma unroll
        for (int half = 0; half < 2; half++) {
            const int i = r0 + r + half*8;
            const int p = i >> 1, n = i & 1;
            const int gy = (wi*8 + (p >> 3) + SHIFT) & 127;
            const int gx = (wj*8 + (p & 7) + SHIFT) & 127;
            float* o = out + (size_t)((((b*128 + gy)*128 + gx)*2 + n)*128) + h*32;
            #pragma unroll
            for (int nt = 0; nt < 4; nt++) {
                const int j = nt*8 + cq*2;
                float2 e = *(const float2*)(sOE + i*ES + j);
                float2 rv;
                rv.x = d[nt][half*2 + 0] + e.x;
                rv.y = d[nt][half*2 + 1] + e.y;
                *(float2*)(o + j) = rv;
            }
        }
    }
}

extern "C" void kernel_launch(void* const* d_in, const int* in_sizes, int n_in,
                              void* d_out, int out_size)
{
    const float* qkv  = (const float*)d_in[0];
    const float* mask = (const float*)d_in[1];
    const float* rpe  = (const float*)d_in[2];
    cudaFuncSetAttribute(swin_attn_kernel,
                         cudaFuncAttributeMaxDynamicSharedMemorySize, SMEM_BYTES);
    dim3 grid(1024, 4);
    swin_attn_kernel<<<grid, 256, SMEM_BYTES>>>(qkv, mask, rpe, (float*)d_out);
}

// round 17
// speedup vs baseline: 1.1956x; 1.1956x over previous
#include <cuda_runtime.h>
#include <cuda_bf16.h>
#include <cstdint>

#define SHIFT 4
#define NR 225
#define SCALE 0.17677669529663687f

// smem byte offsets
#define QH_B   0          // bf16 q hi token-major 20u32/row (10240)
#define QL_B   10240
#define KH_B   20480
#define KL_B   30720
#define QE_B   40960      // bf16 q_embed 225x40 (18432 pad)
#define KE_B   59392      // bf16 k_embed
#define VET_B  77824      // bf16 VE^T 32x240 (15360)
#define G1_B   93184      // bf16 G1 128x232 (59392; region 61440 for W overlay)
#define G2_B   154624     // bf16 G2 128x232 (59392)
#define SMEM_BYTES 214016
// overlays
#define VTH_B  0          // bf16 V^T hi 32x136 (8704)  [over QH, dead after G1]
#define VTL_B  10240      // bf16 V^T lo              [over QL, dead after qk]
#define W_B    93184      // bf16 W 128x240 (61440)    [over G1, dead after qr gather]

__device__ __forceinline__ void mma_bf16(float* d, uint32_t a0, uint32_t a1, uint32_t a2, uint32_t a3,
                                         uint32_t b0, uint32_t b1) {
    asm volatile(
        "mma.sync.aligned.m16n8k16.row.col.f32.bf16.bf16.f32 "
        "{%0,%1,%2,%3},{%4,%5,%6,%7},{%8,%9},{%0,%1,%2,%3};"
        : "+f"(d[0]), "+f"(d[1]), "+f"(d[2]), "+f"(d[3])
        : "r"(a0), "r"(a1), "r"(a2), "r"(a3), "r"(b0), "r"(b1));
}
__device__ __forceinline__ uint32_t pkhi(float a, float b) {
    __nv_bfloat162 t = __floats2bfloat162_rn(a, b);
    return *reinterpret_cast<uint32_t*>(&t);
}
__device__ __forceinline__ uint32_t pklo(float a, float b) {
    float ha = __bfloat162float(__float2bfloat16(a));
    float hb = __bfloat162float(__float2bfloat16(b));
    __nv_bfloat162 t = __floats2bfloat162_rn(a - ha, b - hb);
    return *reinterpret_cast<uint32_t*>(&t);
}

__global__ __launch_bounds__(256, 1)
void swin_attn_kernel(const float* __restrict__ qkv,
                      const float* __restrict__ mask,
                      const float* __restrict__ rpe,
                      float* __restrict__ out)
{
    extern __shared__ char smc[];
    uint32_t* QHu = (uint32_t*)(smc + QH_B);
    uint32_t* QLu = (uint32_t*)(smc + QL_B);
    uint32_t* KHu = (uint32_t*)(smc + KH_B);
    uint32_t* KLu = (uint32_t*)(smc + KL_B);
    uint32_t* QEu = (uint32_t*)(smc + QE_B);
    uint32_t* KEu = (uint32_t*)(smc + KE_B);
    __nv_bfloat16* QEb = (__nv_bfloat16*)(smc + QE_B);
    __nv_bfloat16* KEb = (__nv_bfloat16*)(smc + KE_B);
    uint32_t* VEtu = (uint32_t*)(smc + VET_B);
    __nv_bfloat16* VEtb = (__nv_bfloat16*)(smc + VET_B);
    uint32_t* G1u = (uint32_t*)(smc + G1_B);
    __nv_bfloat16* G1b = (__nv_bfloat16*)(smc + G1_B);
    uint32_t* G2u = (uint32_t*)(smc + G2_B);
    __nv_bfloat16* G2b = (__nv_bfloat16*)(smc + G2_B);
    uint32_t* Wu = (uint32_t*)(smc + W_B);
    __nv_bfloat16* Wb = (__nv_bfloat16*)(smc + W_B);
    uint32_t* VTHu = (uint32_t*)(smc + VTH_B);
    uint32_t* VTLu = (uint32_t*)(smc + VTL_B);

    const int tid = threadIdx.x, wid = tid >> 5, lane = tid & 31;
    const int h   = blockIdx.y;
    const int b   = blockIdx.x >> 8;
    const int win = blockIdx.x & 255;
    const int wi  = win >> 4, wj = win & 15;

    // ---- loads: q/k hi-lo tiles, QE/KE tables, VE^T ----
    {
        const int t = tid >> 1, half = tid & 1;
        const int wh = t >> 4, ww = (t >> 1) & 7, n = t & 1;
        const int gy = (wi*8 + wh + SHIFT) & 127;
        const int gx = (wj*8 + ww + SHIFT) & 127;
        const float* base = qkv + (size_t)((((b*128 + gy)*128 + gx)*2 + n)*384) + h*32 + half*16;
        #pragma unroll
        for (int c4 = 0; c4 < 4; c4++) {
            float4 q = ((const float4*)base)[c4];
            float4 k = ((const float4*)(base + 128))[c4];
            q.x *= SCALE; q.y *= SCALE; q.z *= SCALE; q.w *= SCALE;
            const int u = t*20 + half*8 + c4*2;
            QHu[u]   = pkhi(q.x, q.y); QHu[u+1] = pkhi(q.z, q.w);
            QLu[u]   = pklo(q.x, q.y); QLu[u+1] = pklo(q.z, q.w);
            KHu[u]   = pkhi(k.x, k.y); KHu[u+1] = pkhi(k.z, k.w);
            KLu[u]   = pklo(k.x, k.y); KLu[u+1] = pklo(k.z, k.w);
        }
    }
    for (int idx = tid; idx < NR*16; idx += 256) {
        const int r = idx >> 4, s = idx & 15;
        const int sl = s >> 3, c4 = s & 7;
        float4 v = *(const float4*)(rpe + (size_t)r*384 + h*96 + sl*32 + c4*4);
        __nv_bfloat16* dst = sl ? KEb : QEb;
        if (sl == 0) { v.x *= SCALE; v.y *= SCALE; v.z *= SCALE; v.w *= SCALE; }
        uint2 pk;
        pk.x = pkhi(v.x, v.y); pk.y = pkhi(v.z, v.w);
        *(uint2*)(dst + r*40 + c4*4) = pk;
    }
    for (int idx = tid; idx < NR*32; idx += 256) {
        const int c = idx / NR, r = idx - c*NR;
        VEtb[c*240 + r] = __float2bfloat16(rpe[(size_t)r*384 + h*96 + 64 + c]);
    }
    for (int idx = tid; idx < 32*15; idx += 256) {
        const int c = idx / 15, m = idx - c*15;
        VEtb[c*240 + 225 + m] = __float2bfloat16(0.f);
    }
    __syncthreads();

    const int r0 = wid*16, rw = lane >> 2, cq = lane & 3;
    const int i0 = r0 + rw, i1 = i0 + 8;
    const int p0 = i0 >> 1, ph0 = p0 >> 3, pw0 = p0 & 7;
    const int p1 = i1 >> 1, ph1 = p1 >> 3, pw1 = p1 & 7;

    // ---- qk logits in registers + mask ----
    float acc[16][4];
    #pragma unroll
    for (int nt = 0; nt < 16; nt++)
        #pragma unroll
        for (int e = 0; e < 4; e++) acc[nt][e] = 0.f;
    {
        uint32_t ah[2][4], al[2][4];
        #pragma unroll
        for (int kt = 0; kt < 2; kt++) {
            const int base0 = i0*20 + kt*8 + cq;
            const int base1 = i1*20 + kt*8 + cq;
            ah[kt][0] = QHu[base0];     ah[kt][1] = QHu[base1];
            ah[kt][2] = QHu[base0 + 4]; ah[kt][3] = QHu[base1 + 4];
            al[kt][0] = QLu[base0];     al[kt][1] = QLu[base1];
            al[kt][2] = QLu[base0 + 4]; al[kt][3] = QLu[base1 + 4];
        }
        const float* mrow = mask + (size_t)win*16384;
        #pragma unroll
        for (int nt = 0; nt < 16; nt++) {
            #pragma unroll
            for (int kt = 0; kt < 2; kt++) {
                const int bidx = (nt*8 + rw)*20 + kt*8 + cq;
                uint32_t bh0 = KHu[bidx], bh1 = KHu[bidx + 4];
                uint32_t bl0 = KLu[bidx], bl1 = KLu[bidx + 4];
                mma_bf16(acc[nt], ah[kt][0], ah[kt][1], ah[kt][2], ah[kt][3], bh0, bh1);
                mma_bf16(acc[nt], al[kt][0], al[kt][1], al[kt][2], al[kt][3], bh0, bh1);
                mma_bf16(acc[nt], ah[kt][0], ah[kt][1], ah[kt][2], ah[kt][3], bl0, bl1);
            }
            const int j0 = nt*8 + cq*2;
            float2 m0 = *(const float2*)(mrow + i0*128 + j0);
            float2 m1 = *(const float2*)(mrow + i1*128 + j0);
            acc[nt][0] += m0.x; acc[nt][1] += m0.y;
            acc[nt][2] += m1.x; acc[nt][3] += m1.y;
        }
    }

    // ---- G1 = Qh @ KEh^T (rows warp-private) ----
    {
        uint32_t a[2][4];
        #pragma unroll
        for (int kt = 0; kt < 2; kt++) {
            const int base0 = i0*20 + kt*8 + cq;
            const int base1 = i1*20 + kt*8 + cq;
            a[kt][0] = QHu[base0]; a[kt][1] = QHu[base1];
            a[kt][2] = QHu[base0 + 4]; a[kt][3] = QHu[base1 + 4];
        }
        #pragma unroll 4
        for (int nt = 0; nt < 29; nt++) {
            float d4[4] = {0.f, 0.f, 0.f, 0.f};
            #pragma unroll
            for (int kt = 0; kt < 2; kt++) {
                const int bidx = (nt*8 + rw)*20 + kt*8 + cq;
                mma_bf16(d4, a[kt][0], a[kt][1], a[kt][2], a[kt][3], KEu[bidx], KEu[bidx + 4]);
            }
            G1u[i0*116 + nt*4 + cq] = pkhi(d4[0], d4[1]);
            G1u[i1*116 + nt*4 + cq] = pkhi(d4[2], d4[3]);
        }
    }
    // ---- qr gather (own rows of G1) ----
    #pragma unroll
    for (int nt = 0; nt < 16; nt++) {
        const int pj = nt*4 + cq, pjh = pj >> 3, pjw = pj & 7;
        const int rA = (ph0 - pjh + 7)*15 + (pw0 - pjw + 7);
        const int rB = (ph1 - pjh + 7)*15 + (pw1 - pjw + 7);
        float g0 = __bfloat162float(G1b[i0*232 + rA]);
        float g1 = __bfloat162float(G1b[i1*232 + rB]);
        acc[nt][0] += g0; acc[nt][1] += g0;
        acc[nt][2] += g1; acc[nt][3] += g1;
    }
    // ---- G2 = Kh @ QEh^T ----
    {
        uint32_t a[2][4];
        #pragma unroll
        for (int kt = 0; kt < 2; kt++) {
            const int base0 = i0*20 + kt*8 + cq;
            const int base1 = i1*20 + kt*8 + cq;
            a[kt][0] = KHu[base0]; a[kt][1] = KHu[base1];
            a[kt][2] = KHu[base0 + 4]; a[kt][3] = KHu[base1 + 4];
        }
        #pragma unroll 4
        for (int nt = 0; nt < 29; nt++) {
            float d4[4] = {0.f, 0.f, 0.f, 0.f};
            #pragma unroll
            for (int kt = 0; kt < 2; kt++) {
                const int bidx = (nt*8 + rw)*20 + kt*8 + cq;
                mma_bf16(d4, a[kt][0], a[kt][1], a[kt][2], a[kt][3], QEu[bidx], QEu[bidx + 4]);
            }
            G2u[i0*116 + nt*4 + cq] = pkhi(d4[0], d4[1]);
            G2u[i1*116 + nt*4 + cq] = pkhi(d4[2], d4[3]);
        }
    }
    __syncthreads();   // G2 visible to all; q/k tiles dead

    // ---- load V -> V^T hi/lo (over dead QH/QL) ----
    {
        const int t = tid >> 1, half = tid & 1;
        const int wh = t >> 4, ww = (t >> 1) & 7, n = t & 1;
        const int gy = (wi*8 + wh + SHIFT) & 127;
        const int gx = (wj*8 + ww + SHIFT) & 127;
        const float* vbase = qkv + (size_t)((((b*128 + gy)*128 + gx)*2 + n)*384) + 256 + h*32 + half*16;
        #pragma unroll
        for (int c4 = 0; c4 < 4; c4++) {
            float4 v = ((const float4*)vbase)[c4];
            float vv[4] = {v.x, v.y, v.z, v.w};
            #pragma unroll
            for (int e = 0; e < 4; e++) {
                const int c = half*16 + c4*4 + e;
                __nv_bfloat16 hi = __float2bfloat16(vv[e]);
                __nv_bfloat16 lo = __float2bfloat16(vv[e] - __bfloat162float(hi));
                ((__nv_bfloat16*)VTHu)[c*136 + t] = hi;
                ((__nv_bfloat16*)VTLu)[c*136 + t] = lo;
            }
        }
    }
    // ---- kr gather ----
    #pragma unroll
    for (int nt = 0; nt < 16; nt++) {
        const int j0 = nt*8 + cq*2;
        const int pj = j0 >> 1, pjh = pj >> 3, pjw = pj & 7;
        const int rA = (ph0 - pjh + 7)*15 + (pw0 - pjw + 7);
        const int rB = (ph1 - pjh + 7)*15 + (pw1 - pjw + 7);
        acc[nt][0] += __bfloat162float(G2b[j0*232 + rA]);
        acc[nt][1] += __bfloat162float(G2b[(j0+1)*232 + rA]);
        acc[nt][2] += __bfloat162float(G2b[j0*232 + rB]);
        acc[nt][3] += __bfloat162float(G2b[(j0+1)*232 + rB]);
    }
    // ---- softmax in registers (quad shfl) ----
    #pragma unroll
    for (int rv = 0; rv < 2; rv++) {
        float m = -1e30f;
        #pragma unroll
        for (int nt = 0; nt < 16; nt++)
            m = fmaxf(m, fmaxf(acc[nt][rv*2], acc[nt][rv*2+1]));
        m = fmaxf(m, __shfl_xor_sync(~0u, m, 1));
        m = fmaxf(m, __shfl_xor_sync(~0u, m, 2));
        float s = 0.f;
        #pragma unroll
        for (int nt = 0; nt < 16; nt++) {
            acc[nt][rv*2]   = __expf(acc[nt][rv*2]   - m);
            acc[nt][rv*2+1] = __expf(acc[nt][rv*2+1] - m);
            s += acc[nt][rv*2] + acc[nt][rv*2+1];
        }
        s += __shfl_xor_sync(~0u, s, 1);
        s += __shfl_xor_sync(~0u, s, 2);
        const float inv = 1.f / s;
        #pragma unroll
        for (int nt = 0; nt < 16; nt++) {
            acc[nt][rv*2]   *= inv;
            acc[nt][rv*2+1] *= inv;
        }
    }
    // ---- W: zero own rows, scatter pair sums (over dead G1) ----
    #pragma unroll 4
    for (int m = 0; m < 60; m++) Wu[r0*120 + m*32 + lane] = 0;
    __syncwarp();
    #pragma unroll
    for (int nt = 0; nt < 16; nt++) {
        const int pj = nt*4 + cq, pjh = pj >> 3, pjw = pj & 7;
        const int rA = (ph0 - pjh + 7)*15 + (pw0 - pjw + 7);
        const int rB = (ph1 - pjh + 7)*15 + (pw1 - pjw + 7);
        Wb[i0*240 + rA] = __float2bfloat16(acc[nt][0] + acc[nt][1]);
        Wb[i1*240 + rB] = __float2bfloat16(acc[nt][2] + acc[nt][3]);
    }
    __syncwarp();

    // ---- OE GEMM: d += W(own rows) @ VE^T ----
    float d[4][4];
    #pragma unroll
    for (int nt = 0; nt < 4; nt++)
        #pragma unroll
        for (int e = 0; e < 4; e++) d[nt][e] = 0.f;
    #pragma unroll 3
    for (int kt = 0; kt < 15; kt++) {
        const int a0i = i0*120 + kt*8 + cq;
        const int a1i = i1*120 + kt*8 + cq;
        uint32_t a0 = Wu[a0i], a1 = Wu[a1i], a2 = Wu[a0i + 4], a3 = Wu[a1i + 4];
        #pragma unroll
        for (int nt = 0; nt < 4; nt++) {
            const int bidx = (nt*8 + rw)*120 + kt*8 + cq;
            mma_bf16(d[nt], a0, a1, a2, a3, VEtu[bidx], VEtu[bidx + 4]);
        }
    }
    __syncthreads();   // V^T ready

    // ---- AV: A-frags packed from acc regs, B from V^T hi/lo ----
    #pragma unroll
    for (int kt = 0; kt < 8; kt++) {
        uint32_t ah0 = pkhi(acc[2*kt][0],   acc[2*kt][1]);
        uint32_t ah1 = pkhi(acc[2*kt][2],   acc[2*kt][3]);
        uint32_t ah2 = pkhi(acc[2*kt+1][0], acc[2*kt+1][1]);
        uint32_t ah3 = pkhi(acc[2*kt+1][2], acc[2*kt+1][3]);
        uint32_t al0 = pklo(acc[2*kt][0],   acc[2*kt][1]);
        uint32_t al1 = pklo(acc[2*kt][2],   acc[2*kt][3]);
        uint32_t al2 = pklo(acc[2*kt+1][0], acc[2*kt+1][1]);
        uint32_t al3 = pklo(acc[2*kt+1][2], acc[2*kt+1][3]);
        #pragma unroll
        for (int nt = 0; nt < 4; nt++) {
            const int bidx = (nt*8 + rw)*68 + kt*8 + cq;
            uint32_t bh0 = VTHu[bidx], bh1 = VTHu[bidx + 4];
            uint32_t bl0 = VTLu[bidx], bl1 = VTLu[bidx + 4];
            mma_bf16(d[nt], ah0, ah1, ah2, ah3, bh0, bh1);
            mma_bf16(d[nt], al0, al1, al2, al3, bh0, bh1);
            mma_bf16(d[nt], ah0, ah1, ah2, ah3, bl0, bl1);
        }
    }
    // ---- store ----
    #pragma unroll
    for (int half = 0; half < 2; half++) {
        const int i = half ? i1 : i0;
        const int p = i >> 1, n = i & 1;
        const int gy = (wi*8 + (p >> 3) + SHIFT) & 127;
        const int gx = (wj*8 + (p & 7) + SHIFT) & 127;
        float* o = out + (size_t)((((b*128 + gy)*128 + gx)*2 + n)*128) + h*32;
        #pragma unroll
        for (int nt = 0; nt < 4; nt++) {
            const int j = nt*8 + cq*2;
            float2 rv;
            rv.x = d[nt][half*2 + 0];
            rv.y = d[nt][half*2 + 1];
            *(float2*)(o + j) = rv;
        }
    }
}

extern "C" void kernel_launch(void* const* d_in, const int* in_sizes, int n_in,
                              void* d_out, int out_size)
{
    const float* qkv  = (const float*)d_in[0];
    const float* mask = (const float*)d_in[1];
    const float* rpe  = (const float*)d_in[2];
    cudaFuncSetAttribute(swin_attn_kernel,
                         cudaFuncAttributeMaxDynamicSharedMemorySize, SMEM_BYTES);
    dim3 grid(1024, 4);
    swin_attn_kernel<<<grid, 256, SMEM_BYTES>>>(qkv, mask, rpe, (float*)d_out);
}